// round 15
// baseline (speedup 1.0000x reference)
#include <cuda_runtime.h>

#define Wd 192
#define Hd 192
#define HW (Wd * Hd)
#define Hm 190
#define Wm 190
#define NBG 32     // B*G = 2*16
#define SPLIT 10
#define RS 19      // rows per strip (190/10)
#define TROWS (RS + 2)          // tile rows per plane (19 + 2 border)
#define PLSTRIDE (TROWS * Wd)   // floats per plane tile

// Scratch (device globals; no runtime allocation)
__device__ double g_part[288 * SPLIT * 36];  // partial triangular grams
__device__ int    g_nnA[NBG * 9];
__device__ int    g_nnK[NBG * 9];
__device__ float  g_cnt[NBG * 9];

// ---------------------------------------------------------------------------
// Kernel A (R12-best): per (bg, j, strip) partial 8x8 gram of motif rows.
// Motif row c -> flat F=8j+c -> (a=F/9, k=F%9); value = feat[a, k/3+y, k%3+x].
// 8 rows span <=2 adjacent planes -> smem tiles; J compile-time -> LDS imm.
// ---------------------------------------------------------------------------
template<int J>
__device__ __forceinline__ void gram_body(const float* __restrict__ fb,
                                          const int strip, const int blk,
                                          float* __restrict__ tile,
                                          float (*part)[36]) {
    constexpr int A_LO = (8 * J) / 9;
    constexpr int A_HI = (8 * J + 7) / 9;
    constexpr int NPL  = (A_HI == A_LO) ? 1 : 2;
    constexpr int V4_PER_PL = TROWS * (Wd / 4);

    const int y0 = strip * RS;
    {
        float4* t4 = (float4*)tile;
        for (int i = threadIdx.x; i < NPL * V4_PER_PL; i += 192) {
            const int pl  = i / V4_PER_PL;
            const int rem = i - pl * V4_PER_PL;
            const int rr  = rem / (Wd / 4);
            const int c4  = rem - rr * (Wd / 4);
            const float4* src =
                (const float4*)(fb + (size_t)(A_LO + pl) * HW + (y0 + rr) * Wd) + c4;
            t4[i] = *src;
        }
    }
    __syncthreads();

    float acc[36];
#pragma unroll
    for (int t = 0; t < 36; t++) acc[t] = 0.f;

    const int x = threadIdx.x;
    if (x < Wm) {
        int base = x;
#pragma unroll 2
        for (int r = 0; r < RS; r++) {
            float m[8];
#pragma unroll
            for (int c = 0; c < 8; c++) {
                const int F = 8 * J + c;          // compile-time
                const int a = F / 9, k = F % 9;   // compile-time
                m[c] = tile[(a - A_LO) * PLSTRIDE + (k / 3) * Wd + (k % 3) + base];
            }
            int t = 0;
#pragma unroll
            for (int c = 0; c < 8; c++)
#pragma unroll
                for (int d = c; d < 8; d++) {
                    acc[t] += m[c] * m[d];
                    t++;
                }
            base += Wd;
        }
    }

    const int lane = threadIdx.x & 31, wid = threadIdx.x >> 5;
#pragma unroll
    for (int t = 0; t < 36; t++) {
#pragma unroll
        for (int sh = 16; sh > 0; sh >>= 1)
            acc[t] += __shfl_down_sync(0xffffffffu, acc[t], sh);
    }
    if (lane == 0) {
#pragma unroll
        for (int t = 0; t < 36; t++) part[wid][t] = acc[t];
    }
    __syncthreads();

    if (threadIdx.x < 36) {
        double s = 0.0;
#pragma unroll
        for (int w6 = 0; w6 < 6; w6++) s += (double)part[w6][threadIdx.x];
        g_part[((size_t)blk * SPLIT + strip) * 36 + threadIdx.x] = s;
    }
}

__global__ __launch_bounds__(192) void motif_gram_kernel(const float* __restrict__ f) {
    const int blk   = blockIdx.x;     // 0..287 = bg*9 + j
    const int strip = blockIdx.y;     // 0..SPLIT-1
    const int bg    = blk / 9;
    const int j     = blk % 9;
    const float* fb = f + (size_t)bg * 8 * HW;

    __shared__ __align__(16) float tile[2 * PLSTRIDE];   // 32256 B
    __shared__ float part[6][36];

    switch (j) {   // block-uniform branch
        case 0: gram_body<0>(fb, strip, blk, tile, part); break;
        case 1: gram_body<1>(fb, strip, blk, tile, part); break;
        case 2: gram_body<2>(fb, strip, blk, tile, part); break;
        case 3: gram_body<3>(fb, strip, blk, tile, part); break;
        case 4: gram_body<4>(fb, strip, blk, tile, part); break;
        case 5: gram_body<5>(fb, strip, blk, tile, part); break;
        case 6: gram_body<6>(fb, strip, blk, tile, part); break;
        case 7: gram_body<7>(fb, strip, blk, tile, part); break;
        default: gram_body<8>(fb, strip, blk, tile, part); break;
    }
}

// ---------------------------------------------------------------------------
// Kernel B: reduce strip partials -> grams; argmin (diag excluded, first-min
// tie-break); per j: u = max nn, cnt = #{nn==u}.
// ---------------------------------------------------------------------------
__global__ __launch_bounds__(128) void motif_argmin_kernel() {
    const int bg = blockIdx.x;
    const int t  = threadIdx.x;
    __shared__ double G[9 * 64];
    __shared__ int nn[72];

    for (int e = t; e < 9 * 36; e += 128) {
        const int j = e / 36;
        int rem = e % 36, c = 0;
        while (rem >= 8 - c) { rem -= (8 - c); c++; }
        const int d = c + rem;
        double sum = 0.0;
#pragma unroll
        for (int sl = 0; sl < SPLIT; sl++)
            sum += g_part[((size_t)(bg * 9 + j) * SPLIT + sl) * 36 + (e % 36)];
        G[j * 64 + c * 8 + d] = sum;
        G[j * 64 + d * 8 + c] = sum;
    }
    __syncthreads();

    if (t < 72) {
        const int j = t / 8, c = t % 8;
        const double* gj = G + j * 64;
        const double scc = gj[c * 8 + c];
        double best = 1e300;
        int bi = 0;
        for (int d = 0; d < 8; d++) {
            if (d == c) continue;
            const double d2 = scc + gj[d * 8 + d] - 2.0 * gj[c * 8 + d];
            if (d2 < best) { best = d2; bi = d; }
        }
        nn[t] = bi;
    }
    __syncthreads();

    if (t < 9) {
        int u = 0, cnt = 0;
        for (int c = 0; c < 8; c++) u = max(u, nn[t * 8 + c]);
        for (int c = 0; c < 8; c++) cnt += (nn[t * 8 + c] == u) ? 1 : 0;
        const int fn = 8 * t + u;
        g_nnA[bg * 9 + t] = fn / 9;
        g_nnK[bg * 9 + t] = fn % 9;
        g_cnt[bg * 9 + t] = (float)cnt;
    }
}

// ---------------------------------------------------------------------------
// Kernel C (R12 flat, best-known): gather form of the fold.
// out = mask*nvalid*self + sum_k valid floor((self*nb) * (cnt_k/8))
// IDEMPOTENT: launched twice this round to measure its in-graph duration
// (total - baseline_105 = C). Second launch rewrites identical values.
// ---------------------------------------------------------------------------
__global__ __launch_bounds__(256) void motif_out_kernel(const float* __restrict__ f,
                                                        float* __restrict__ out) {
    const int bc = blockIdx.x;        // b*128 + cglob
    const int b = bc >> 7, cglob = bc & 127;
    const int g = cglob >> 3, cnew = cglob & 7;
    const int bg = b * 16 + g;

    __shared__ int   off9[9];
    __shared__ float cs9[9];          // cnt * 0.125 (exact)
    if (threadIdx.x < 9) {
        const int knew = threadIdx.x;
        const int j = (cnew * 9 + knew) >> 3;
        const int an = g_nnA[bg * 9 + j];
        const int kn = g_nnK[bg * 9 + j];
        cs9[knew] = g_cnt[bg * 9 + j] * 0.125f;
        const int dh = kn / 3 - knew / 3;
        const int dw = kn % 3 - knew % 3;
        off9[knew] = (an - cnew) * HW + dh * Wd + dw;
    }
    __syncthreads();

    int   offr[9];
    float csr[9];
#pragma unroll
    for (int k = 0; k < 9; k++) { offr[k] = off9[k]; csr[k] = cs9[k]; }

    const float* fc = f + (size_t)bc * HW;
    float* oc = out + (size_t)bc * HW;
    const float mask = (b != 0) ? 1.0f : 0.0f;

    const int start = blockIdx.y * (HW / 12);   // 3072 px per chunk
    const int end   = start + (HW / 12);

    for (int idx = start + threadIdx.x; idx < end; idx += 256) {
        const int h = idx / Wd;
        const int w = idx - h * Wd;
        const float self = fc[idx];
        float acc = 0.f;
        float nvf;

        if (h >= 2 && h <= Hd - 3 && w >= 2 && w <= Wd - 3) {   // interior
            nvf = 9.0f;
#pragma unroll
            for (int k = 0; k < 9; k++) {
                const float nb = fc[idx + offr[k]];
                float tv = self * nb;       // fl(m*mn), matches reference
                tv = tv * csr[k];           // = fl(tv*cnt)*2^-3 exactly
                acc += floorf(tv);
            }
        } else {
            const int kiLo = max(0, h - (Hm - 1)), kiHi = min(2, h);
            const int kjLo = max(0, w - (Wm - 1)), kjHi = min(2, w);
            nvf = (float)((kiHi - kiLo + 1) * (kjHi - kjLo + 1));
            for (int ki = kiLo; ki <= kiHi; ki++)
                for (int kj = kjLo; kj <= kjHi; kj++) {
                    const int k = ki * 3 + kj;
                    const float nb = fc[idx + offr[k]];
                    float tv = self * nb;
                    tv = tv * csr[k];
                    acc += floorf(tv);
                }
        }
        oc[idx] = acc + mask * nvf * self;
    }
}

extern "C" void kernel_launch(void* const* d_in, const int* in_sizes, int n_in,
                              void* d_out, int out_size) {
    const float* f = (const float*)d_in[0];
    float* out = (float*)d_out;
    (void)in_sizes; (void)n_in; (void)out_size;

    motif_gram_kernel<<<dim3(288, SPLIT), 192>>>(f);
    motif_argmin_kernel<<<32, 128>>>();
    // Launched twice (idempotent) to measure C's in-graph duration:
    // total - ~105 = C. Remove the duplicate next round.
    motif_out_kernel<<<dim3(256, 12), 256>>>(f, out);
    motif_out_kernel<<<dim3(256, 12), 256>>>(f, out);
}

// round 16
// speedup vs baseline: 1.5272x; 1.5272x over previous
#include <cuda_runtime.h>

#define Wd 192
#define Hd 192
#define HW (Wd * Hd)
#define Hm 190
#define Wm 190
#define NBG 32     // B*G = 2*16
#define SPLIT 10
#define RS 19      // rows per strip (190/10)
#define TROWS (RS + 2)          // tile rows per plane (19 + 2 border)
#define PLSTRIDE (TROWS * Wd)   // floats per plane tile

// Scratch (device globals; no runtime allocation)
__device__ double g_part[288 * SPLIT * 36];  // partial triangular grams
__device__ int    g_nnA[NBG * 9];
__device__ int    g_nnK[NBG * 9];
__device__ float  g_cnt[NBG * 9];

// ---------------------------------------------------------------------------
// Kernel A (R12-best): per (bg, j, strip) partial 8x8 gram of motif rows.
// Motif row c -> flat F=8j+c -> (a=F/9, k=F%9); value = feat[a, k/3+y, k%3+x].
// 8 rows span <=2 adjacent planes -> smem tiles; J compile-time -> LDS imm.
// ---------------------------------------------------------------------------
template<int J>
__device__ __forceinline__ void gram_body(const float* __restrict__ fb,
                                          const int strip, const int blk,
                                          float* __restrict__ tile,
                                          float (*part)[36]) {
    constexpr int A_LO = (8 * J) / 9;
    constexpr int A_HI = (8 * J + 7) / 9;
    constexpr int NPL  = (A_HI == A_LO) ? 1 : 2;
    constexpr int V4_PER_PL = TROWS * (Wd / 4);

    const int y0 = strip * RS;
    {
        float4* t4 = (float4*)tile;
        for (int i = threadIdx.x; i < NPL * V4_PER_PL; i += 192) {
            const int pl  = i / V4_PER_PL;
            const int rem = i - pl * V4_PER_PL;
            const int rr  = rem / (Wd / 4);
            const int c4  = rem - rr * (Wd / 4);
            const float4* src =
                (const float4*)(fb + (size_t)(A_LO + pl) * HW + (y0 + rr) * Wd) + c4;
            t4[i] = *src;
        }
    }
    __syncthreads();

    float acc[36];
#pragma unroll
    for (int t = 0; t < 36; t++) acc[t] = 0.f;

    const int x = threadIdx.x;
    if (x < Wm) {
        int base = x;
#pragma unroll 2
        for (int r = 0; r < RS; r++) {
            float m[8];
#pragma unroll
            for (int c = 0; c < 8; c++) {
                const int F = 8 * J + c;          // compile-time
                const int a = F / 9, k = F % 9;   // compile-time
                m[c] = tile[(a - A_LO) * PLSTRIDE + (k / 3) * Wd + (k % 3) + base];
            }
            int t = 0;
#pragma unroll
            for (int c = 0; c < 8; c++)
#pragma unroll
                for (int d = c; d < 8; d++) {
                    acc[t] += m[c] * m[d];
                    t++;
                }
            base += Wd;
        }
    }

    const int lane = threadIdx.x & 31, wid = threadIdx.x >> 5;
#pragma unroll
    for (int t = 0; t < 36; t++) {
#pragma unroll
        for (int sh = 16; sh > 0; sh >>= 1)
            acc[t] += __shfl_down_sync(0xffffffffu, acc[t], sh);
    }
    if (lane == 0) {
#pragma unroll
        for (int t = 0; t < 36; t++) part[wid][t] = acc[t];
    }
    __syncthreads();

    if (threadIdx.x < 36) {
        double s = 0.0;
#pragma unroll
        for (int w6 = 0; w6 < 6; w6++) s += (double)part[w6][threadIdx.x];
        g_part[((size_t)blk * SPLIT + strip) * 36 + threadIdx.x] = s;
    }
}

__global__ __launch_bounds__(192) void motif_gram_kernel(const float* __restrict__ f) {
    const int blk   = blockIdx.x;     // 0..287 = bg*9 + j
    const int strip = blockIdx.y;     // 0..SPLIT-1
    const int bg    = blk / 9;
    const int j     = blk % 9;
    const float* fb = f + (size_t)bg * 8 * HW;

    __shared__ __align__(16) float tile[2 * PLSTRIDE];   // 32256 B
    __shared__ float part[6][36];

    switch (j) {   // block-uniform branch
        case 0: gram_body<0>(fb, strip, blk, tile, part); break;
        case 1: gram_body<1>(fb, strip, blk, tile, part); break;
        case 2: gram_body<2>(fb, strip, blk, tile, part); break;
        case 3: gram_body<3>(fb, strip, blk, tile, part); break;
        case 4: gram_body<4>(fb, strip, blk, tile, part); break;
        case 5: gram_body<5>(fb, strip, blk, tile, part); break;
        case 6: gram_body<6>(fb, strip, blk, tile, part); break;
        case 7: gram_body<7>(fb, strip, blk, tile, part); break;
        default: gram_body<8>(fb, strip, blk, tile, part); break;
    }
}

// ---------------------------------------------------------------------------
// Kernel B: reduce strip partials -> grams; argmin (diag excluded, first-min
// tie-break); per j: u = max nn, cnt = #{nn==u}.
// ---------------------------------------------------------------------------
__global__ __launch_bounds__(128) void motif_argmin_kernel() {
    const int bg = blockIdx.x;
    const int t  = threadIdx.x;
    __shared__ double G[9 * 64];
    __shared__ int nn[72];

    for (int e = t; e < 9 * 36; e += 128) {
        const int j = e / 36;
        int rem = e % 36, c = 0;
        while (rem >= 8 - c) { rem -= (8 - c); c++; }
        const int d = c + rem;
        double sum = 0.0;
#pragma unroll
        for (int sl = 0; sl < SPLIT; sl++)
            sum += g_part[((size_t)(bg * 9 + j) * SPLIT + sl) * 36 + (e % 36)];
        G[j * 64 + c * 8 + d] = sum;
        G[j * 64 + d * 8 + c] = sum;
    }
    __syncthreads();

    if (t < 72) {
        const int j = t / 8, c = t % 8;
        const double* gj = G + j * 64;
        const double scc = gj[c * 8 + c];
        double best = 1e300;
        int bi = 0;
        for (int d = 0; d < 8; d++) {
            if (d == c) continue;
            const double d2 = scc + gj[d * 8 + d] - 2.0 * gj[c * 8 + d];
            if (d2 < best) { best = d2; bi = d; }
        }
        nn[t] = bi;
    }
    __syncthreads();

    if (t < 9) {
        int u = 0, cnt = 0;
        for (int c = 0; c < 8; c++) u = max(u, nn[t * 8 + c]);
        for (int c = 0; c < 8; c++) cnt += (nn[t * 8 + c] == u) ? 1 : 0;
        const int fn = 8 * t + u;
        g_nnA[bg * 9 + t] = fn / 9;
        g_nnK[bg * 9 + t] = fn % 9;
        g_cnt[bg * 9 + t] = (float)cnt;
    }
}

// ---------------------------------------------------------------------------
// Kernel C: branch-free, division-free gather fold.
// Every pixel runs one uniform 9-term body; invalid terms contribute
// floor(+-0) = +-0 via cs->0 select (exactly zero effect); offsets clamped to
// self for address safety. (h,w) tracked incrementally (chunk = 16 full rows).
// out = mask*nvalid*self + sum_k floor((self*nb) * (cnt_k/8))
// ---------------------------------------------------------------------------
__global__ __launch_bounds__(256) void motif_out_kernel(const float* __restrict__ f,
                                                        float* __restrict__ out) {
    const int bc = blockIdx.x;        // b*128 + cglob
    const int b = bc >> 7, cglob = bc & 127;
    const int g = cglob >> 3, cnew = cglob & 7;
    const int bg = b * 16 + g;

    __shared__ int   off9[9];
    __shared__ float cs9[9];          // cnt * 0.125 (exact)
    if (threadIdx.x < 9) {
        const int knew = threadIdx.x;
        const int j = (cnew * 9 + knew) >> 3;
        const int an = g_nnA[bg * 9 + j];
        const int kn = g_nnK[bg * 9 + j];
        cs9[knew] = g_cnt[bg * 9 + j] * 0.125f;
        const int dh = kn / 3 - knew / 3;
        const int dw = kn % 3 - knew % 3;
        off9[knew] = (an - cnew) * HW + dh * Wd + dw;
    }
    __syncthreads();

    int   offr[9];
    float csr[9];
#pragma unroll
    for (int k = 0; k < 9; k++) { offr[k] = off9[k]; csr[k] = cs9[k]; }

    const float* fc = f + (size_t)bc * HW;
    float* oc = out + (size_t)bc * HW;
    const float mask = (b != 0) ? 1.0f : 0.0f;

    // chunk = 16 complete rows (3072 px); 12 iterations of 256 threads.
    const int start = blockIdx.y * (16 * Wd);
    int idx = start + threadIdx.x;
    int h = blockIdx.y * 16 + (threadIdx.x >= Wd ? 1 : 0);
    int w = threadIdx.x - (threadIdx.x >= Wd ? Wd : 0);

#pragma unroll 1
    for (int it = 0; it < 12; it++) {
        // validity: patch row (h-ki) in [0,Hm-1]; col (w-kj) in [0,Wm-1]
        const bool hv[3] = {((unsigned)h       <= (Hm - 1)),
                            ((unsigned)(h - 1) <= (Hm - 1)),
                            ((unsigned)(h - 2) <= (Hm - 1))};
        const bool wv[3] = {((unsigned)w       <= (Wm - 1)),
                            ((unsigned)(w - 1) <= (Wm - 1)),
                            ((unsigned)(w - 2) <= (Wm - 1))};
        const int nv = ((int)hv[0] + (int)hv[1] + (int)hv[2])
                     * ((int)wv[0] + (int)wv[1] + (int)wv[2]);

        const float self = fc[idx];
        float acc = 0.f;
#pragma unroll
        for (int k = 0; k < 9; k++) {
            const bool v = hv[k / 3] & wv[k % 3];       // k/3,k%3 compile-time
            const int  o = v ? offr[k] : 0;             // safe address
            const float cs = v ? csr[k] : 0.0f;         // invalid -> floor(+-0)
            const float nb = fc[idx + o];
            float tv = self * nb;       // fl(m*mn), matches reference
            tv = tv * cs;               // = fl(tv*cnt)*2^-3 exactly (or +-0)
            acc += floorf(tv);
        }
        oc[idx] = acc + mask * (float)nv * self;

        // advance 256 px = +1 row + 64 cols (branchless wrap)
        idx += 256;
        w += 64; h += 1;
        if (w >= Wd) { w -= Wd; h += 1; }
    }
}

extern "C" void kernel_launch(void* const* d_in, const int* in_sizes, int n_in,
                              void* d_out, int out_size) {
    const float* f = (const float*)d_in[0];
    float* out = (float*)d_out;
    (void)in_sizes; (void)n_in; (void)out_size;

    motif_gram_kernel<<<dim3(288, SPLIT), 192>>>(f);
    motif_argmin_kernel<<<32, 128>>>();
    motif_out_kernel<<<dim3(256, 12), 256>>>(f, out);
}

// round 17
// speedup vs baseline: 2.0888x; 1.3677x over previous
#include <cuda_runtime.h>

#define Wd 192
#define Hd 192
#define HW (Wd * Hd)
#define Hm 190
#define Wm 190
#define NBG 32     // B*G = 2*16
#define SPLIT 10
#define RS 19      // rows per strip (190/10)
#define TROWS (RS + 2)          // tile rows per plane (19 + 2 border)
#define PLSTRIDE (TROWS * Wd)   // floats per plane tile

#define FLOOR_MAGIC 12582912.0f // 1.5 * 2^23; fadd_rd(x,M)-M == floor(x), |x|<2^22

// Scratch (device globals; no runtime allocation)
__device__ double g_part[288 * SPLIT * 36];  // partial triangular grams
__device__ int    g_nnA[NBG * 9];
__device__ int    g_nnK[NBG * 9];
__device__ float  g_cnt[NBG * 9];

// ---------------------------------------------------------------------------
// Kernel A (R12-best): per (bg, j, strip) partial 8x8 gram of motif rows.
// Motif row c -> flat F=8j+c -> (a=F/9, k=F%9); value = feat[a, k/3+y, k%3+x].
// 8 rows span <=2 adjacent planes -> smem tiles; J compile-time -> LDS imm.
// ---------------------------------------------------------------------------
template<int J>
__device__ __forceinline__ void gram_body(const float* __restrict__ fb,
                                          const int strip, const int blk,
                                          float* __restrict__ tile,
                                          float (*part)[36]) {
    constexpr int A_LO = (8 * J) / 9;
    constexpr int A_HI = (8 * J + 7) / 9;
    constexpr int NPL  = (A_HI == A_LO) ? 1 : 2;
    constexpr int V4_PER_PL = TROWS * (Wd / 4);

    const int y0 = strip * RS;
    {
        float4* t4 = (float4*)tile;
        for (int i = threadIdx.x; i < NPL * V4_PER_PL; i += 192) {
            const int pl  = i / V4_PER_PL;
            const int rem = i - pl * V4_PER_PL;
            const int rr  = rem / (Wd / 4);
            const int c4  = rem - rr * (Wd / 4);
            const float4* src =
                (const float4*)(fb + (size_t)(A_LO + pl) * HW + (y0 + rr) * Wd) + c4;
            t4[i] = *src;
        }
    }
    __syncthreads();

    float acc[36];
#pragma unroll
    for (int t = 0; t < 36; t++) acc[t] = 0.f;

    const int x = threadIdx.x;
    if (x < Wm) {
        int base = x;
#pragma unroll 2
        for (int r = 0; r < RS; r++) {
            float m[8];
#pragma unroll
            for (int c = 0; c < 8; c++) {
                const int F = 8 * J + c;          // compile-time
                const int a = F / 9, k = F % 9;   // compile-time
                m[c] = tile[(a - A_LO) * PLSTRIDE + (k / 3) * Wd + (k % 3) + base];
            }
            int t = 0;
#pragma unroll
            for (int c = 0; c < 8; c++)
#pragma unroll
                for (int d = c; d < 8; d++) {
                    acc[t] += m[c] * m[d];
                    t++;
                }
            base += Wd;
        }
    }

    const int lane = threadIdx.x & 31, wid = threadIdx.x >> 5;
#pragma unroll
    for (int t = 0; t < 36; t++) {
#pragma unroll
        for (int sh = 16; sh > 0; sh >>= 1)
            acc[t] += __shfl_down_sync(0xffffffffu, acc[t], sh);
    }
    if (lane == 0) {
#pragma unroll
        for (int t = 0; t < 36; t++) part[wid][t] = acc[t];
    }
    __syncthreads();

    if (threadIdx.x < 36) {
        double s = 0.0;
#pragma unroll
        for (int w6 = 0; w6 < 6; w6++) s += (double)part[w6][threadIdx.x];
        g_part[((size_t)blk * SPLIT + strip) * 36 + threadIdx.x] = s;
    }
}

__global__ __launch_bounds__(192) void motif_gram_kernel(const float* __restrict__ f) {
    const int blk   = blockIdx.x;     // 0..287 = bg*9 + j
    const int strip = blockIdx.y;     // 0..SPLIT-1
    const int bg    = blk / 9;
    const int j     = blk % 9;
    const float* fb = f + (size_t)bg * 8 * HW;

    __shared__ __align__(16) float tile[2 * PLSTRIDE];   // 32256 B
    __shared__ float part[6][36];

    switch (j) {   // block-uniform branch
        case 0: gram_body<0>(fb, strip, blk, tile, part); break;
        case 1: gram_body<1>(fb, strip, blk, tile, part); break;
        case 2: gram_body<2>(fb, strip, blk, tile, part); break;
        case 3: gram_body<3>(fb, strip, blk, tile, part); break;
        case 4: gram_body<4>(fb, strip, blk, tile, part); break;
        case 5: gram_body<5>(fb, strip, blk, tile, part); break;
        case 6: gram_body<6>(fb, strip, blk, tile, part); break;
        case 7: gram_body<7>(fb, strip, blk, tile, part); break;
        default: gram_body<8>(fb, strip, blk, tile, part); break;
    }
}

// ---------------------------------------------------------------------------
// Kernel B: reduce strip partials -> grams; argmin (diag excluded, first-min
// tie-break); per j: u = max nn, cnt = #{nn==u}.
// ---------------------------------------------------------------------------
__global__ __launch_bounds__(128) void motif_argmin_kernel() {
    const int bg = blockIdx.x;
    const int t  = threadIdx.x;
    __shared__ double G[9 * 64];
    __shared__ int nn[72];

    for (int e = t; e < 9 * 36; e += 128) {
        const int j = e / 36;
        int rem = e % 36, c = 0;
        while (rem >= 8 - c) { rem -= (8 - c); c++; }
        const int d = c + rem;
        double sum = 0.0;
#pragma unroll
        for (int sl = 0; sl < SPLIT; sl++)
            sum += g_part[((size_t)(bg * 9 + j) * SPLIT + sl) * 36 + (e % 36)];
        G[j * 64 + c * 8 + d] = sum;
        G[j * 64 + d * 8 + c] = sum;
    }
    __syncthreads();

    if (t < 72) {
        const int j = t / 8, c = t % 8;
        const double* gj = G + j * 64;
        const double scc = gj[c * 8 + c];
        double best = 1e300;
        int bi = 0;
        for (int d = 0; d < 8; d++) {
            if (d == c) continue;
            const double d2 = scc + gj[d * 8 + d] - 2.0 * gj[c * 8 + d];
            if (d2 < best) { best = d2; bi = d; }
        }
        nn[t] = bi;
    }
    __syncthreads();

    if (t < 9) {
        int u = 0, cnt = 0;
        for (int c = 0; c < 8; c++) u = max(u, nn[t * 8 + c]);
        for (int c = 0; c < 8; c++) cnt += (nn[t * 8 + c] == u) ? 1 : 0;
        const int fn = 8 * t + u;
        g_nnA[bg * 9 + t] = fn / 9;
        g_nnK[bg * 9 + t] = fn % 9;
        g_cnt[bg * 9 + t] = (float)cnt;
    }
}

// ---------------------------------------------------------------------------
// Kernel C-interior: h in [2,189], w in [2,189] — all 9 terms valid, no
// validity logic. 9 base pointers computed once per thread; all loads use
// compile-time immediate offsets (r*Wd). Floor via exact magic add (fma pipe).
// out = 9*mask*self + sum_k floor((self*nb_k) * (cnt_k/8))
// ---------------------------------------------------------------------------
__global__ __launch_bounds__(192) void motif_out_interior(const float* __restrict__ f,
                                                          float* __restrict__ out) {
    const int bc = blockIdx.x;        // b*128 + cglob
    const int b = bc >> 7, cglob = bc & 127;
    const int g = cglob >> 3, cnew = cglob & 7;
    const int bg = b * 16 + g;

    __shared__ int   off9[9];
    __shared__ float cs9[9];          // cnt * 0.125 (exact)
    if (threadIdx.x < 9) {
        const int knew = threadIdx.x;
        const int j = (cnew * 9 + knew) >> 3;
        const int an = g_nnA[bg * 9 + j];
        const int kn = g_nnK[bg * 9 + j];
        cs9[knew] = g_cnt[bg * 9 + j] * 0.125f;
        const int dh = kn / 3 - knew / 3;
        const int dw = kn % 3 - knew % 3;
        off9[knew] = (an - cnew) * HW + dh * Wd + dw;
    }
    __syncthreads();

    const int t = threadIdx.x;
    if (t >= 188) return;                       // w = 2 + t in [2,189]

    const float* fc = f + (size_t)bc * HW;
    float* oc = out + (size_t)bc * HW;
    const float msk9 = (b != 0) ? 9.0f : 0.0f;

    const int h0   = 2 + blockIdx.y * 4;        // rows h0..h0+3 (2..189)
    const int idx0 = h0 * Wd + 2 + t;

    const float* pk[9];
    float cs[9];
#pragma unroll
    for (int k = 0; k < 9; k++) {
        pk[k] = fc + idx0 + off9[k];            // stays inside the 8-plane group
        cs[k] = cs9[k];
    }
    const float* ps = fc + idx0;
    float* po = oc + idx0;

#pragma unroll
    for (int r = 0; r < 4; r++) {               // r*Wd = compile-time LDG imm
        const float self = ps[r * Wd];
        float acc = 0.f;
#pragma unroll
        for (int k = 0; k < 9; k++) {
            const float nb = pk[k][r * Wd];
            float tv = self * nb;               // fl(m*mn), matches reference
            tv = tv * cs[k];                    // = fl(tv*cnt)*2^-3 exactly
            const float y = __fadd_rd(tv, FLOOR_MAGIC);
            acc += (y - FLOOR_MAGIC);           // exact floor(tv)
        }
        po[r * Wd] = acc + msk9 * self;
    }
}

// ---------------------------------------------------------------------------
// Kernel C-boundary: the 1520-px frame per plane (rows 0,1,190,191 full +
// cols 0,1,190,191 of rows 2..189). R12 dynamic validity logic.
// ---------------------------------------------------------------------------
__global__ __launch_bounds__(256) void motif_out_boundary(const float* __restrict__ f,
                                                          float* __restrict__ out) {
    const int bc = blockIdx.x;
    const int b = bc >> 7, cglob = bc & 127;
    const int g = cglob >> 3, cnew = cglob & 7;
    const int bg = b * 16 + g;

    __shared__ int   off9[9];
    __shared__ float cs9[9];
    if (threadIdx.x < 9) {
        const int knew = threadIdx.x;
        const int j = (cnew * 9 + knew) >> 3;
        const int an = g_nnA[bg * 9 + j];
        const int kn = g_nnK[bg * 9 + j];
        cs9[knew] = g_cnt[bg * 9 + j] * 0.125f;
        const int dh = kn / 3 - knew / 3;
        const int dw = kn % 3 - knew % 3;
        off9[knew] = (an - cnew) * HW + dh * Wd + dw;
    }
    __syncthreads();

    const float* fc = f + (size_t)bc * HW;
    float* oc = out + (size_t)bc * HW;
    const float mask = (b != 0) ? 1.0f : 0.0f;

    for (int i = threadIdx.x; i < 1520; i += 256) {
        int h, w;
        if (i < 384)      { h = i / Wd;               w = i % Wd; }
        else if (i < 768) { h = 190 + (i - 384) / Wd; w = (i - 384) % Wd; }
        else {
            const int j2 = i - 768;
            const int q  = j2 & 3;
            h = 2 + (j2 >> 2);                   // rows 2..189
            w = (q < 2) ? q : 188 + q;           // 0,1,190,191
        }
        const int idx = h * Wd + w;
        const float self = fc[idx];
        float acc = 0.f;

        const int kiLo = max(0, h - (Hm - 1)), kiHi = min(2, h);
        const int kjLo = max(0, w - (Wm - 1)), kjHi = min(2, w);
        const float nvf = (float)((kiHi - kiLo + 1) * (kjHi - kjLo + 1));
        for (int ki = kiLo; ki <= kiHi; ki++)
            for (int kj = kjLo; kj <= kjHi; kj++) {
                const int k = ki * 3 + kj;
                const float nb = fc[idx + off9[k]];
                float tv = self * nb;
                tv = tv * cs9[k];
                acc += floorf(tv);
            }
        oc[idx] = acc + mask * nvf * self;
    }
}

extern "C" void kernel_launch(void* const* d_in, const int* in_sizes, int n_in,
                              void* d_out, int out_size) {
    const float* f = (const float*)d_in[0];
    float* out = (float*)d_out;
    (void)in_sizes; (void)n_in; (void)out_size;

    motif_gram_kernel<<<dim3(288, SPLIT), 192>>>(f);
    motif_argmin_kernel<<<32, 128>>>();
    motif_out_interior<<<dim3(256, 47), 192>>>(f, out);
    motif_out_boundary<<<256, 256>>>(f, out);
}